// round 11
// baseline (speedup 1.0000x reference)
#include <cuda_runtime.h>
#include <cstdint>

// Problem constants
#define Bsz 4
#define Tsz 4096
#define Isz 2048
#define Esz 16
#define Jsz 128
#define Csz 1024

#define BM 128
#define BN 128
#define BK 32
#define NTHREADS 256            // 8 warps: 2 (M) x 4 (N), warp tile 64x32
#define NITER (Isz / BK)        // 64
#define STAGES 3
#define PITCH 36                // u32 per row: 32 data + 4 pad (conflict-free)
#define TILE_FLOATS (BM * PITCH)          // 4608
#define STAGE_FLOATS (2 * TILE_FLOATS)    // 9216
#define DYN_SMEM (STAGES * STAGE_FLOATS * 4)   // 110592 B

// Truncation-bias compensation: HMMA reads raw fp32 as tf32 (RZ truncation).
// Validated R7/R9: rel_err 3.1e-4.
#define CORR 1.000678f

__device__ __forceinline__ void mma_tf32(float c[4], const uint32_t a[4], const uint32_t b[2]) {
    asm volatile(
        "mma.sync.aligned.m16n8k8.row.col.f32.tf32.tf32.f32 "
        "{%0,%1,%2,%3}, {%4,%5,%6,%7}, {%8,%9}, {%0,%1,%2,%3};\n"
        : "+f"(c[0]), "+f"(c[1]), "+f"(c[2]), "+f"(c[3])
        : "r"(a[0]), "r"(a[1]), "r"(a[2]), "r"(a[3]), "r"(b[0]), "r"(b[1]));
}

__device__ __forceinline__ void cp_async16(uint32_t smem_addr, const void* gptr) {
    asm volatile("cp.async.cg.shared.global [%0], [%1], 16;\n"
                 :: "r"(smem_addr), "l"(gptr));
}
__device__ __forceinline__ void cp_commit() {
    asm volatile("cp.async.commit_group;\n" ::: "memory");
}
template <int N>
__device__ __forceinline__ void cp_wait() {
    asm volatile("cp.async.wait_group %0;\n" :: "n"(N) : "memory");
}

__global__ void __launch_bounds__(NTHREADS, 2)
gather_gemm_tf32(const float* __restrict__ X,
                 const void* __restrict__ ind_raw,
                 const float* __restrict__ W,
                 float* __restrict__ out)
{
    extern __shared__ uint32_t smem[];   // [STAGES][A|B][BM][PITCH]
    __shared__ int sIdx[BM];
    __shared__ int sIs64;

    const int mtile = blockIdx.x;   // 0..7
    const int e     = blockIdx.y;   // 0..15
    const int b     = blockIdx.z;   // 0..3
    const int tid   = threadIdx.x;
    const int lane  = tid & 31;
    const int warp  = tid >> 5;
    const int wm    = warp & 1;     // 0..1  (M offset 64)
    const int wn    = warp >> 1;    // 0..3  (N offset 32)

    // ---- dtype sniff: int64 vs int32 indices (values < 4096 -> int64 odd words zero)
    if (warp == 0) {
        const uint32_t* iw = (const uint32_t*)ind_raw;
        uint32_t oddw = iw[2 * lane + 1];
        unsigned mask = __ballot_sync(0xFFFFFFFFu, oddw == 0u);
        if (lane == 0) sIs64 = (mask == 0xFFFFFFFFu) ? 1 : 0;
    }
    __syncthreads();
    const int is64 = sIs64;

    if (tid < BM) {
        size_t p = ((size_t)b * Esz + e) * Csz + (size_t)mtile * BM + tid;
        int t;
        if (is64) t = (int)((const long long*)ind_raw)[p];
        else      t = ((const int*)ind_raw)[p];
        sIdx[tid] = t;
    }
    __syncthreads();

    const float* Xb = X + (size_t)b * Tsz * Isz;
    const float* Wb = W + (size_t)e * Jsz * Isz;

    // producer assignment: 8 threads per row; thread covers 4 A rows and 4 B rows
    // (trow + 32r), one 16B chunk per row.
    const int trow = tid >> 3;        // 0..31
    const int c4   = (tid & 7) * 4;   // float col within BK

    // 32-bit gmem offsets (X block spans 32M floats; W tile 256K floats)
    uint32_t aOff[4], bOff[4];
    uint32_t dstA[4], dstB[4];        // smem byte addrs within stage 0
    const uint32_t smemBase = (uint32_t)__cvta_generic_to_shared(smem);
#pragma unroll
    for (int r = 0; r < 4; r++) {
        int m = trow + r * 32;
        aOff[r] = (uint32_t)(sIdx[m] * Isz + c4);
        bOff[r] = (uint32_t)(m * Isz + c4);
        dstA[r] = smemBase + (uint32_t)((m * PITCH + c4) * 4);
        dstB[r] = smemBase + (uint32_t)((TILE_FLOATS + m * PITCH + c4) * 4);
    }

    float acc[4][4][4];
#pragma unroll
    for (int i = 0; i < 4; i++)
#pragma unroll
        for (int j = 0; j < 4; j++)
#pragma unroll
            for (int r = 0; r < 4; r++) acc[i][j][r] = 0.0f;

    const int g = lane >> 2;   // 0..7
    const int q = lane & 3;    // 0..3

    // ---- prologue: issue stages 0 and 1
#pragma unroll
    for (int s = 0; s < 2; s++) {
        const uint32_t off = (uint32_t)(s * STAGE_FLOATS * 4);
        const int k0 = s * BK;
#pragma unroll
        for (int r = 0; r < 4; r++) {
            cp_async16(dstA[r] + off, Xb + aOff[r] + k0);
            cp_async16(dstB[r] + off, Wb + bOff[r] + k0);
        }
        cp_commit();
    }

    // single-buffered fragments (keeps regs under the 128 cap; 4 warps/SMSP
    // provide the latency coverage instead of per-warp double buffering)
    uint32_t ar[4][4];
    uint32_t br[4][2];

#define LOADFRAG(KS)                                                          \
    {                                                                         \
        const int _kk = (KS) * 8;                                             \
        _Pragma("unroll")                                                     \
        for (int i = 0; i < 4; i++) {                                         \
            int m0 = wm * 64 + i * 16;                                        \
            ar[i][0] = cA[(m0 + g)     * PITCH + _kk + q];                    \
            ar[i][1] = cA[(m0 + g + 8) * PITCH + _kk + q];                    \
            ar[i][2] = cA[(m0 + g)     * PITCH + _kk + q + 4];                \
            ar[i][3] = cA[(m0 + g + 8) * PITCH + _kk + q + 4];                \
        }                                                                     \
        _Pragma("unroll")                                                     \
        for (int j = 0; j < 4; j++) {                                         \
            int n0 = wn * 32 + j * 8;                                         \
            br[j][0] = cB[(n0 + g) * PITCH + _kk + q];                        \
            br[j][1] = cB[(n0 + g) * PITCH + _kk + q + 4];                    \
        }                                                                     \
    }

    int sc = 0;   // stage being computed
    int si = 2;   // stage being issued
    for (int it = 0; it < NITER; it++) {
        // cp_wait is PER-THREAD: the barrier after it is what makes ALL
        // threads' copies for stage sc visible. No smem read may precede it.
        cp_wait<1>();
        __syncthreads();

        const uint32_t* cA = smem + sc * STAGE_FLOATS;
        const uint32_t* cB = cA + TILE_FLOATS;

        // ks=0 fragments on the critical path, then issue next stage's cp.async
        LOADFRAG(0);

        if (it + 2 < NITER) {
            const uint32_t off = (uint32_t)(si * STAGE_FLOATS * 4);
            const int k0 = (it + 2) * BK;
#pragma unroll
            for (int r = 0; r < 4; r++) {
                cp_async16(dstA[r] + off, Xb + aOff[r] + k0);
                cp_async16(dstB[r] + off, Wb + bOff[r] + k0);
            }
            cp_commit();
        }

#pragma unroll
        for (int ks = 0; ks < 4; ks++) {
#pragma unroll
            for (int i = 0; i < 4; i++)
#pragma unroll
                for (int j = 0; j < 4; j++)
                    mma_tf32(acc[i][j], ar[i], br[j]);
            if (ks < 3) LOADFRAG(ks + 1);
        }

        if (++sc == STAGES) sc = 0;
        if (++si == STAGES) si = 0;
    }

    // ---- epilogue: apply truncation-bias compensation, then store
    float* outp = out + (((size_t)b * Esz + e) * Csz + (size_t)mtile * BM) * Jsz;
#pragma unroll
    for (int i = 0; i < 4; i++) {
        int row0 = wm * 64 + i * 16 + g;
#pragma unroll
        for (int j = 0; j < 4; j++) {
            int col = wn * 32 + j * 8 + 2 * q;
            *(float2*)(outp + (size_t)row0 * Jsz + col) =
                make_float2(acc[i][j][0] * CORR, acc[i][j][1] * CORR);
            *(float2*)(outp + (size_t)(row0 + 8) * Jsz + col) =
                make_float2(acc[i][j][2] * CORR, acc[i][j][3] * CORR);
        }
    }
}

extern "C" void kernel_launch(void* const* d_in, const int* in_sizes, int n_in,
                              void* d_out, int out_size)
{
    const float* X   = (const float*)d_in[0];
    const void*  ind = (const void*)d_in[1];
    const float* W   = (const float*)d_in[2];
    float* out = (float*)d_out;

    cudaFuncSetAttribute(gather_gemm_tf32,
                         cudaFuncAttributeMaxDynamicSharedMemorySize, DYN_SMEM);

    dim3 grid(Csz / BM, Esz, Bsz);   // (8, 16, 4) = 512 CTAs
    dim3 block(NTHREADS);
    gather_gemm_tf32<<<grid, block, DYN_SMEM>>>(X, ind, W, out);
}

// round 12
// speedup vs baseline: 1.6532x; 1.6532x over previous
#include <cuda_runtime.h>
#include <cstdint>

// Problem constants
#define Bsz 4
#define Tsz 4096
#define Isz 2048
#define Esz 16
#define Jsz 128
#define Csz 1024

#define BM 128
#define BN 128
#define BK 32
#define NTHREADS 128            // 4 warps: 2 (M) x 2 (N), warp tile 64x64
#define NITER (Isz / BK)        // 64
#define PITCH 20                // u32 per row: 16 data (32 fp16) + 4 pad
#define TILE_U32 (BM * PITCH)   // 2560
#define STAGE_U32 (2 * TILE_U32)          // A tile + B tile
#define DYN_SMEM (2 * STAGE_U32 * 4)      // 40960 B (2 stages)

// Pack two fp32 -> one u32 of fp16x2 (round-to-nearest-even; unbiased, so no
// epilogue correction needed). Low half = first element (little-endian k order).
__device__ __forceinline__ uint32_t pack_f16x2(float lo, float hi) {
    uint32_t r;
    asm("cvt.rn.f16x2.f32 %0, %1, %2;" : "=r"(r) : "f"(hi), "f"(lo));
    return r;
}

__device__ __forceinline__ void sts64(uint32_t* addr, uint32_t x, uint32_t y) {
    asm volatile("st.shared.v2.b32 [%0], {%1,%2};" :: "l"(addr), "r"(x), "r"(y) : "memory");
}

__device__ __forceinline__ void mma_f16(float c[4], const uint32_t a[4], const uint32_t b[2]) {
    asm volatile(
        "mma.sync.aligned.m16n8k16.row.col.f32.f16.f16.f32 "
        "{%0,%1,%2,%3}, {%4,%5,%6,%7}, {%8,%9}, {%0,%1,%2,%3};\n"
        : "+f"(c[0]), "+f"(c[1]), "+f"(c[2]), "+f"(c[3])
        : "r"(a[0]), "r"(a[1]), "r"(a[2]), "r"(a[3]), "r"(b[0]), "r"(b[1]));
}

__global__ void __launch_bounds__(NTHREADS, 2)
gather_gemm_f16(const float* __restrict__ X,
                const void* __restrict__ ind_raw,
                const float* __restrict__ W,
                float* __restrict__ out)
{
    extern __shared__ uint32_t smem[];   // [2 stages][A(128x20) | B(128x20)] u32
    __shared__ int sIdx[BM];
    __shared__ int sIs64;

    const int mtile = blockIdx.x;   // 0..7
    const int e     = blockIdx.y;   // 0..15
    const int b     = blockIdx.z;   // 0..3
    const int tid   = threadIdx.x;
    const int lane  = tid & 31;
    const int warp  = tid >> 5;
    const int wm    = warp & 1;     // 0..1
    const int wn    = warp >> 1;    // 0..1

    // ---- dtype sniff: int64 vs int32 indices (values < 4096 -> int64 odd words zero)
    if (warp == 0) {
        const uint32_t* iw = (const uint32_t*)ind_raw;
        uint32_t oddw = iw[2 * lane + 1];
        unsigned mask = __ballot_sync(0xFFFFFFFFu, oddw == 0u);
        if (lane == 0) sIs64 = (mask == 0xFFFFFFFFu) ? 1 : 0;
    }
    __syncthreads();
    const int is64 = sIs64;

    {
        size_t p = ((size_t)b * Esz + e) * Csz + (size_t)mtile * BM + tid;
        int t;
        if (is64) t = (int)((const long long*)ind_raw)[p];
        else      t = ((const int*)ind_raw)[p];
        sIdx[tid] = t;
    }
    __syncthreads();

    const float* Xb = X + (size_t)b * Tsz * Isz;
    const float* Wb = W + (size_t)e * Jsz * Isz;

    // producer assignment: thread covers 8 rows (trow + 16r), one 16B fp32 chunk
    // per row (4 floats -> 2 u32 of fp16x2 -> STS.64)
    const int trow = tid >> 3;        // 0..15
    const int c4   = (tid & 7) * 4;   // float col within BK
    const int h2   = (tid & 7) * 2;   // u32 col within fp16 tile row

    uint32_t aOff[8], bOff[8];        // 32-bit gmem float offsets
    uint32_t* dstA[8];
    uint32_t* dstB[8];
#pragma unroll
    for (int r = 0; r < 8; r++) {
        int m = trow + r * 16;
        aOff[r] = (uint32_t)(sIdx[m] * Isz + c4);
        bOff[r] = (uint32_t)(m * Isz + c4);
        dstA[r] = smem + m * PITCH + h2;
        dstB[r] = smem + TILE_U32 + m * PITCH + h2;
    }

    float acc[4][8][4];
#pragma unroll
    for (int i = 0; i < 4; i++)
#pragma unroll
        for (int j = 0; j < 8; j++)
#pragma unroll
            for (int r = 0; r < 4; r++) acc[i][j][r] = 0.0f;

    const int g = lane >> 2;   // 0..7
    const int q = lane & 3;    // 0..3

    // ---- prologue: tile 0 into registers
    float4 ra[8], rb[8];
#pragma unroll
    for (int r = 0; r < 8; r++) {
        ra[r] = *(const float4*)(Xb + aOff[r]);
        rb[r] = *(const float4*)(Wb + bOff[r]);
    }

    for (int it = 0; it < NITER; it++) {
        uint32_t* stage = smem + (it & 1) * STAGE_U32;

        // store current tile (fp32 -> fp16x2 on the way in)
#pragma unroll
        for (int r = 0; r < 8; r++) {
            sts64(stage + (dstA[r] - smem),
                  pack_f16x2(ra[r].x, ra[r].y), pack_f16x2(ra[r].z, ra[r].w));
            sts64(stage + (dstB[r] - smem),
                  pack_f16x2(rb[r].x, rb[r].y), pack_f16x2(rb[r].z, rb[r].w));
        }

        // prefetch next tile into registers (hidden under this iter's compute)
        if (it + 1 < NITER) {
            const int k0 = (it + 1) * BK;
#pragma unroll
            for (int r = 0; r < 8; r++) {
                ra[r] = *(const float4*)(Xb + aOff[r] + k0);
                rb[r] = *(const float4*)(Wb + bOff[r] + k0);
            }
        }

        __syncthreads();

        const uint32_t* cA = stage;
        const uint32_t* cB = stage + TILE_U32;

        // 2 k16-steps per BK=32
#pragma unroll
        for (int ks = 0; ks < 2; ks++) {
            const int kk = ks * 8;   // u32 offset (16 fp16)
            uint32_t areg[4][4];
            uint32_t breg[8][2];
#pragma unroll
            for (int i = 0; i < 4; i++) {
                int m0 = wm * 64 + i * 16;
                areg[i][0] = cA[(m0 + g)     * PITCH + kk + q];
                areg[i][1] = cA[(m0 + g + 8) * PITCH + kk + q];
                areg[i][2] = cA[(m0 + g)     * PITCH + kk + q + 4];
                areg[i][3] = cA[(m0 + g + 8) * PITCH + kk + q + 4];
            }
#pragma unroll
            for (int j = 0; j < 8; j++) {
                int n0 = wn * 64 + j * 8;
                breg[j][0] = cB[(n0 + g) * PITCH + kk + q];
                breg[j][1] = cB[(n0 + g) * PITCH + kk + q + 4];
            }
#pragma unroll
            for (int i = 0; i < 4; i++)
#pragma unroll
                for (int j = 0; j < 8; j++)
                    mma_f16(acc[i][j], areg[i], breg[j]);
        }
        // WAR on this stage is fenced by the NEXT iteration's barrier (store to
        // this stage happens only after every warp passed that barrier).
    }

    // ---- epilogue (fp16 RN is unbiased: no correction factor)
    float* outp = out + (((size_t)b * Esz + e) * Csz + (size_t)mtile * BM) * Jsz;
#pragma unroll
    for (int i = 0; i < 4; i++) {
        int row0 = wm * 64 + i * 16 + g;
#pragma unroll
        for (int j = 0; j < 8; j++) {
            int col = wn * 64 + j * 8 + 2 * q;
            *(float2*)(outp + (size_t)row0 * Jsz + col) =
                make_float2(acc[i][j][0], acc[i][j][1]);
            *(float2*)(outp + (size_t)(row0 + 8) * Jsz + col) =
                make_float2(acc[i][j][2], acc[i][j][3]);
        }
    }
}

extern "C" void kernel_launch(void* const* d_in, const int* in_sizes, int n_in,
                              void* d_out, int out_size)
{
    const float* X   = (const float*)d_in[0];
    const void*  ind = (const void*)d_in[1];
    const float* W   = (const float*)d_in[2];
    float* out = (float*)d_out;

    cudaFuncSetAttribute(gather_gemm_f16,
                         cudaFuncAttributeMaxDynamicSharedMemorySize, DYN_SMEM);

    dim3 grid(Csz / BM, Esz, Bsz);   // (8, 16, 4) = 512 CTAs
    dim3 block(NTHREADS);
    gather_gemm_f16<<<grid, block, DYN_SMEM>>>(X, ind, W, out);
}

// round 13
// speedup vs baseline: 1.8317x; 1.1080x over previous
#include <cuda_runtime.h>
#include <cstdint>

// Problem constants
#define Bsz 4
#define Tsz 4096
#define Isz 2048
#define Esz 16
#define Jsz 128
#define Csz 1024

#define BM 128
#define BN 128
#define BK 32
#define NTHREADS 128            // 4 warps: 2 (M) x 2 (N), warp tile 64x64
#define NITER (Isz / BK)        // 64
#define PITCH 20                // u32 per row: 16 data (32 fp16) + 4 pad
#define TILE_U32 (BM * PITCH)   // 2560
#define STAGE_U32 (2 * TILE_U32)          // A tile + B tile
#define DYN_SMEM (2 * STAGE_U32 * 4)      // 40960 B (2 stages)

__device__ __forceinline__ uint32_t pack_f16x2(float lo, float hi) {
    uint32_t r;
    asm("cvt.rn.f16x2.f32 %0, %1, %2;" : "=r"(r) : "f"(hi), "f"(lo));
    return r;
}

__device__ __forceinline__ void sts64(uint32_t addr, uint32_t x, uint32_t y) {
    asm volatile("st.shared.v2.b32 [%0], {%1,%2};" :: "r"(addr), "r"(x), "r"(y) : "memory");
}

__device__ __forceinline__ void ldsm_x4(uint32_t& r0, uint32_t& r1, uint32_t& r2,
                                        uint32_t& r3, uint32_t addr) {
    asm volatile("ldmatrix.sync.aligned.m8n8.x4.shared.b16 {%0,%1,%2,%3}, [%4];"
                 : "=r"(r0), "=r"(r1), "=r"(r2), "=r"(r3) : "r"(addr));
}

__device__ __forceinline__ void mma_f16(float c[4], const uint32_t a[4], const uint32_t b[2]) {
    asm volatile(
        "mma.sync.aligned.m16n8k16.row.col.f32.f16.f16.f32 "
        "{%0,%1,%2,%3}, {%4,%5,%6,%7}, {%8,%9}, {%0,%1,%2,%3};\n"
        : "+f"(c[0]), "+f"(c[1]), "+f"(c[2]), "+f"(c[3])
        : "r"(a[0]), "r"(a[1]), "r"(a[2]), "r"(a[3]), "r"(b[0]), "r"(b[1]));
}

__global__ void __launch_bounds__(NTHREADS, 2)
gather_gemm_f16(const float* __restrict__ X,
                const void* __restrict__ ind_raw,
                const float* __restrict__ W,
                float* __restrict__ out)
{
    extern __shared__ uint32_t smem[];   // [2 stages][A(128x20) | B(128x20)] u32
    __shared__ int sIdx[BM];
    __shared__ int sIs64;

    const int mtile = blockIdx.x;   // 0..7
    const int e     = blockIdx.y;   // 0..15
    const int b     = blockIdx.z;   // 0..3
    const int tid   = threadIdx.x;
    const int lane  = tid & 31;
    const int warp  = tid >> 5;
    const int wm    = warp & 1;     // 0..1
    const int wn    = warp >> 1;    // 0..1

    const uint32_t smemAddr = (uint32_t)__cvta_generic_to_shared(smem);

    // ---- dtype sniff: int64 vs int32 indices (values < 4096 -> int64 odd words zero)
    if (warp == 0) {
        const uint32_t* iw = (const uint32_t*)ind_raw;
        uint32_t oddw = iw[2 * lane + 1];
        unsigned mask = __ballot_sync(0xFFFFFFFFu, oddw == 0u);
        if (lane == 0) sIs64 = (mask == 0xFFFFFFFFu) ? 1 : 0;
    }
    __syncthreads();
    const int is64 = sIs64;

    {
        size_t p = ((size_t)b * Esz + e) * Csz + (size_t)mtile * BM + tid;
        int t;
        if (is64) t = (int)((const long long*)ind_raw)[p];
        else      t = ((const int*)ind_raw)[p];
        sIdx[tid] = t;
    }
    __syncthreads();

    const float* Xb = X + (size_t)b * Tsz * Isz;
    const float* Wb = W + (size_t)e * Jsz * Isz;

    // producer assignment: thread covers 8 rows (trow + 16r), one 16B fp32 chunk
    // per row (4 floats -> 2 u32 of fp16x2 -> STS.64)
    const int trow = tid >> 3;        // 0..15
    const int c4   = (tid & 7) * 4;   // float col within BK
    const int h2   = (tid & 7) * 2;   // u32 col within fp16 tile row

    uint32_t aOff[8], bOff[8];        // 32-bit gmem float offsets
    uint32_t stsA[8], stsB[8];        // smem byte addrs within stage 0
#pragma unroll
    for (int r = 0; r < 8; r++) {
        int m = trow + r * 16;
        aOff[r] = (uint32_t)(sIdx[m] * Isz + c4);
        bOff[r] = (uint32_t)(m * Isz + c4);
        stsA[r] = smemAddr + (uint32_t)((m * PITCH + h2) * 4);
        stsB[r] = smemAddr + (uint32_t)((TILE_U32 + m * PITCH + h2) * 4);
    }

    float acc[4][8][4];
#pragma unroll
    for (int i = 0; i < 4; i++)
#pragma unroll
        for (int j = 0; j < 8; j++)
#pragma unroll
            for (int r = 0; r < 4; r++) acc[i][j][r] = 0.0f;

    const int g = lane >> 2;   // 0..7
    const int q = lane & 3;    // 0..3

    // ldmatrix per-thread row addresses (within stage 0):
    // A x4 tile group for warp-row i: matrices (m0..m0+7,k-lo),(m0+8..15,k-lo),
    //   (m0..7,k-hi),(m0+8..15,k-hi); thread t -> row m0+(t&15), col (t>>4)*4 u32.
    const int aRow = wm * 64 + (lane & 15);
    const int aCol = (lane >> 4) * 4;               // u32
    const uint32_t ldsmA0 = smemAddr + (uint32_t)((aRow * PITCH + aCol) * 4);
    // B x4 for j-pair jp: matrices (n0,k-lo),(n0,k-hi),(n0+8,k-lo),(n0+8,k-hi);
    //   thread t -> row n0+((t>>4)<<3)+(t&7), col ((t>>3)&1)*4 u32.
    const int bRow = wn * 64 + ((lane >> 4) << 3) + (lane & 7);
    const int bCol = ((lane >> 3) & 1) * 4;         // u32
    const uint32_t ldsmB0 = smemAddr + (uint32_t)((TILE_U32 + bRow * PITCH + bCol) * 4);

    // ---- prologue: tile 0 into registers
    float4 ra[8], rb[8];
#pragma unroll
    for (int r = 0; r < 8; r++) {
        ra[r] = *(const float4*)(Xb + aOff[r]);
        rb[r] = *(const float4*)(Wb + bOff[r]);
    }

    for (int it = 0; it < NITER; it++) {
        const uint32_t sOff = (uint32_t)((it & 1) * STAGE_U32 * 4);

        // store current tile (fp32 -> fp16x2 on the way in)
#pragma unroll
        for (int r = 0; r < 8; r++) {
            sts64(stsA[r] + sOff, pack_f16x2(ra[r].x, ra[r].y), pack_f16x2(ra[r].z, ra[r].w));
            sts64(stsB[r] + sOff, pack_f16x2(rb[r].x, rb[r].y), pack_f16x2(rb[r].z, rb[r].w));
        }

        // prefetch next tile into registers (hidden under this iter's compute)
        if (it + 1 < NITER) {
            const int k0 = (it + 1) * BK;
#pragma unroll
            for (int r = 0; r < 8; r++) {
                ra[r] = *(const float4*)(Xb + aOff[r] + k0);
                rb[r] = *(const float4*)(Wb + bOff[r] + k0);
            }
        }

        __syncthreads();

        // 2 k16-steps per BK=32
#pragma unroll
        for (int ks = 0; ks < 2; ks++) {
            const uint32_t kOff = sOff + (uint32_t)(ks * 32);   // 8 u32 = 32 B
            uint32_t areg[4][4];
            uint32_t breg[8][2];
#pragma unroll
            for (int i = 0; i < 4; i++)
                ldsm_x4(areg[i][0], areg[i][1], areg[i][2], areg[i][3],
                        ldsmA0 + kOff + (uint32_t)(i * 16 * PITCH * 4));
#pragma unroll
            for (int jp = 0; jp < 4; jp++)
                ldsm_x4(breg[2 * jp][0], breg[2 * jp][1],
                        breg[2 * jp + 1][0], breg[2 * jp + 1][1],
                        ldsmB0 + kOff + (uint32_t)(jp * 16 * PITCH * 4));
#pragma unroll
            for (int i = 0; i < 4; i++)
#pragma unroll
                for (int j = 0; j < 8; j++)
                    mma_f16(acc[i][j], areg[i], breg[j]);
        }
        // WAR on this stage is fenced by the NEXT iteration's barrier.
    }

    // ---- epilogue (fp16 RN is unbiased: no correction factor)
    float* outp = out + (((size_t)b * Esz + e) * Csz + (size_t)mtile * BM) * Jsz;
#pragma unroll
    for (int i = 0; i < 4; i++) {
        int row0 = wm * 64 + i * 16 + g;
#pragma unroll
        for (int j = 0; j < 8; j++) {
            int col = wn * 64 + j * 8 + 2 * q;
            *(float2*)(outp + (size_t)row0 * Jsz + col) =
                make_float2(acc[i][j][0], acc[i][j][1]);
            *(float2*)(outp + (size_t)(row0 + 8) * Jsz + col) =
                make_float2(acc[i][j][2], acc[i][j][3]);
        }
    }
}

extern "C" void kernel_launch(void* const* d_in, const int* in_sizes, int n_in,
                              void* d_out, int out_size)
{
    const float* X   = (const float*)d_in[0];
    const void*  ind = (const void*)d_in[1];
    const float* W   = (const float*)d_in[2];
    float* out = (float*)d_out;

    cudaFuncSetAttribute(gather_gemm_f16,
                         cudaFuncAttributeMaxDynamicSharedMemorySize, DYN_SMEM);

    dim3 grid(Csz / BM, Esz, Bsz);   // (8, 16, 4) = 512 CTAs
    dim3 block(NTHREADS);
    gather_gemm_f16<<<grid, block, DYN_SMEM>>>(X, ind, W, out);
}